// round 5
// baseline (speedup 1.0000x reference)
#include <cuda_runtime.h>

// Inverse 2x2 Haar wavelet — R5: R4 lane-contiguous mapping, 2 j-pairs/thread
// (j2 and j2+32) to double per-thread MLP while staying <=32 regs.
//
// Input  x: [4B, C, H, W] fp32, quadrants k=0..3 at offset k*B*C*H*W
// Output  : [B, C, 2H, 2W] fp32
//
// Per thread (plane, i, j2 in 0..31):
//   loads : 8 x LDG.64  (float2 per quadrant at cols 2*j2 and 64+2*j2)
//   stores: 4 x STG.128 (rows 2i, 2i+1 at cols 4*j2 and 128+4*j2)
// All instructions are perfectly lane-contiguous per warp (256B loads / 512B stores).

static constexpr int H = 128;
static constexpr int W = 128;
static constexpr int JT = 32;                 // j2 slots per row handled by distinct threads
static constexpr long long PLANE_IN  = (long long)H * W;         // 16384
static constexpr long long PLANE_OUT = (long long)(2*H) * (2*W); // 65536

__device__ __forceinline__ void butterfly2(float2 a, float2 b, float2 c, float2 d,
                                           float4& r0, float4& r1) {
    // lane 0
    float s_ad0 = a.x + d.x, d_ad0 = a.x - d.x;
    float s_bc0 = b.x + c.x, d_bc0 = b.x - c.x;
    // lane 1
    float s_ad1 = a.y + d.y, d_ad1 = a.y - d.y;
    float s_bc1 = b.y + c.y, d_bc1 = b.y - c.y;
    // row 2i : e00, e01 interleaved
    r0 = make_float4(0.5f * (s_ad0 - s_bc0), 0.5f * (d_ad0 + d_bc0),
                     0.5f * (s_ad1 - s_bc1), 0.5f * (d_ad1 + d_bc1));
    // row 2i+1 : e10, e11 interleaved
    r1 = make_float4(0.5f * (d_ad0 - d_bc0), 0.5f * (s_ad0 + s_bc0),
                     0.5f * (d_ad1 - d_bc1), 0.5f * (s_ad1 + s_bc1));
}

__global__ __launch_bounds__(256, 8)
void iwt_kernel(const float* __restrict__ x, float* __restrict__ out,
                long long quad_stride,   // B*C*H*W elements between quadrants
                int n_threads)           // planes * H * JT
{
    int tid = blockIdx.x * blockDim.x + threadIdx.x;
    if (tid >= n_threads) return;

    int j2    = tid & (JT - 1);          // 0..31
    int rest  = tid >> 5;
    int i     = rest & (H - 1);          // 0..127
    int plane = rest >> 7;

    long long in_off = (long long)plane * PLANE_IN + (long long)i * W + (long long)j2 * 2;

    const float* p1 = x + in_off;
    const float* p2 = p1 + quad_stride;
    const float* p3 = p2 + quad_stride;
    const float* p4 = p3 + quad_stride;

    // batch all 8 loads for MLP
    float2 aL = __ldg((const float2*)(p1));
    float2 bL = __ldg((const float2*)(p2));
    float2 cL = __ldg((const float2*)(p3));
    float2 dL = __ldg((const float2*)(p4));
    float2 aR = __ldg((const float2*)(p1 + 64));
    float2 bR = __ldg((const float2*)(p2 + 64));
    float2 cR = __ldg((const float2*)(p3 + 64));
    float2 dR = __ldg((const float2*)(p4 + 64));

    long long out_base = (long long)plane * PLANE_OUT
                       + (long long)(2 * i) * (2 * W)
                       + (long long)j2 * 4;
    float* o0 = out + out_base;          // row 2i, left half
    float* o1 = o0 + 2 * W;              // row 2i+1, left half

    float4 r0, r1;
    butterfly2(aL, bL, cL, dL, r0, r1);
    *(float4*)(o0)        = r0;
    *(float4*)(o1)        = r1;

    butterfly2(aR, bR, cR, dR, r0, r1);
    *(float4*)(o0 + 128)  = r0;          // right half: output cols +128
    *(float4*)(o1 + 128)  = r1;
}

extern "C" void kernel_launch(void* const* d_in, const int* in_sizes, int n_in,
                              void* d_out, int out_size) {
    const float* x = (const float*)d_in[0];
    float* out = (float*)d_out;

    long long total = (long long)in_sizes[0];
    long long quad_stride = total / 4;          // B*C*H*W
    long long planes = quad_stride / PLANE_IN;  // B*C
    int n_threads = (int)(planes * H * JT);

    int block = 256;
    int grid = (n_threads + block - 1) / block;
    iwt_kernel<<<grid, block>>>(x, out, quad_stride, n_threads);
}